// round 15
// baseline (speedup 1.0000x reference)
#include <cuda_runtime.h>
#include <cuda_bf16.h>
#include <math.h>
#include <stdint.h>

#define D_MODEL 2048
#define SEQ     1024
#define N_HEADS 32
#define HEAD_DIM 64
#define NB      (SEQ/64)
#define D_FFN   8192
#define VOCAB   50257
#define NEXP    4
#define QKV_STRIDE (3*D_MODEL)

// ---------------- scratch ----------------
__device__ float g_x  [SEQ*D_MODEL];
__device__ float g_qkv[SEQ*3*D_MODEL];
__device__ float g_y  [SEQ*D_MODEL];
__device__ float g_moe[SEQ*D_MODEL];
__device__ float g_wts[NEXP*SEQ];
__device__ float g_var[SEQ];
__device__ float g_h  [(size_t)NEXP*SEQ*D_FFN];

// routing
__device__ int   g_cnt[NEXP];
__device__ int   g_ridx[NEXP*SEQ];
__device__ float g_rwt [NEXP*SEQ];

// bf16 split scratch
__device__ __nv_bfloat16 g_ah[SEQ*D_MODEL];
__device__ __nv_bfloat16 g_al[SEQ*D_MODEL];

// ---------------- PTX helpers ----------------
__device__ __forceinline__ uint32_t smem_u32(const void* p) {
    uint32_t a;
    asm("{ .reg .u64 t; cvta.to.shared.u64 t, %1; cvt.u32.u64 %0, t; }" : "=r"(a) : "l"(p));
    return a;
}
__device__ __forceinline__ void cp_async16(uint32_t dst, const void* src, int src_bytes) {
    asm volatile("cp.async.cg.shared.global [%0], [%1], 16, %2;\n"
                 :: "r"(dst), "l"(src), "r"(src_bytes) : "memory");
}
#define CP_COMMIT() asm volatile("cp.async.commit_group;\n" ::: "memory")

#define STS128(addr, a, b, c, d) \
    asm volatile("st.shared.v4.b32 [%0], {%1,%2,%3,%4};" \
                 :: "r"(addr), "r"(a), "r"(b), "r"(c), "r"(d) : "memory")

__device__ __forceinline__ void ldsm_x4(uint32_t& r0, uint32_t& r1, uint32_t& r2, uint32_t& r3,
                                        uint32_t addr) {
    asm volatile("ldmatrix.sync.aligned.m8n8.x4.shared.b16 {%0,%1,%2,%3}, [%4];"
                 : "=r"(r0), "=r"(r1), "=r"(r2), "=r"(r3) : "r"(addr));
}
__device__ __forceinline__ void mma_bf16(float* c, const uint32_t* a, const uint32_t* b) {
    asm volatile(
        "mma.sync.aligned.m16n8k16.row.col.f32.bf16.bf16.f32 "
        "{%0,%1,%2,%3}, {%4,%5,%6,%7}, {%8,%9}, {%0,%1,%2,%3};"
        : "+f"(c[0]), "+f"(c[1]), "+f"(c[2]), "+f"(c[3])
        : "r"(a[0]), "r"(a[1]), "r"(a[2]), "r"(a[3]), "r"(b[0]), "r"(b[1]));
}
__device__ __forceinline__ void mma_tf32(float* c, const uint32_t* a, const uint32_t* b) {
    asm volatile(
        "mma.sync.aligned.m16n8k8.row.col.f32.tf32.tf32.f32 "
        "{%0,%1,%2,%3}, {%4,%5,%6,%7}, {%8,%9}, {%0,%1,%2,%3};"
        : "+f"(c[0]), "+f"(c[1]), "+f"(c[2]), "+f"(c[3])
        : "r"(a[0]), "r"(a[1]), "r"(a[2]), "r"(a[3]), "r"(b[0]), "r"(b[1]));
}

__device__ __forceinline__ void split2(float a, float b, uint32_t& hi, uint32_t& lo) {
    __nv_bfloat16 ha = __float2bfloat16(a), hb = __float2bfloat16(b);
    __nv_bfloat162 h; h.x = ha; h.y = hb;
    __nv_bfloat162 l;
    l.x = __float2bfloat16(a - __bfloat162float(ha));
    l.y = __float2bfloat16(b - __bfloat162float(hb));
    hi = *(uint32_t*)&h;
    lo = *(uint32_t*)&l;
}

// ================= GEMM common: CTA 128x256, 16 warps (2Mx8N), warp 64x32 =================
#define NSTG_TC 3
#define A_BYTES (128*128)
#define B_BYTES (256*128)
#define STAGE_B (A_BYTES + B_BYTES)
#define GEMM_SMEM_TC (NSTG_TC * STAGE_B)
#define NSTG_TF 4
#define GEMM_SMEM_TF (NSTG_TF * STAGE_B)

// MODE 1: expert-batched up + fused silu·mul -> fp32 H.
// MODE 3: dense rows, split-K via gridDim.z, atomicAdd into zeroed C.
template<int MODE>
__global__ void __launch_bounds__(512, 1) gemm_tc(
    const __nv_bfloat16* __restrict__ Ah, const __nv_bfloat16* __restrict__ Al,
    const float* __restrict__ B0, const float* __restrict__ B1, const float* __restrict__ B2,
    int rPB,
    float* __restrict__ C, int N, int K,
    const int* __restrict__ cntArr, const int* __restrict__ ridxAll,
    long long sB, float* __restrict__ Hout)
{
    const int tid = threadIdx.x;
    const int m0  = blockIdx.x * 128;
    const int n0  = blockIdx.y * 256;

    int M = SEQ;
    int e = 0, kbase = 0, Kc = K;
    const int* ridx = ridxAll;
    const float* b0p = B0; const float* b1p = B1; const float* b2p = B2;

    if (MODE == 1) {
        e = blockIdx.z;
        M = cntArr[e];
        if (m0 >= M) return;
        ridx = ridxAll + e * SEQ;
        b0p = B0 + (size_t)e * sB;
        b1p = B1 + (size_t)e * sB;
    } else {
        Kc = K / (int)gridDim.z;
        kbase = (int)blockIdx.z * Kc;
    }

    int arow[2];
    #pragma unroll
    for (int i = 0; i < 2; i++) {
        int r = (tid + i * 512) >> 3;
        int rg = m0 + r;
        if (MODE == 3) arow[i] = rg;
        else {
            rg = rg < M ? rg : (M - 1);
            arow[i] = ridx[rg];
        }
    }

    extern __shared__ char smem[];
    const uint32_t sb = smem_u32(smem);
    const int wid = tid >> 5, lid = tid & 31;
    const int wm  = wid >> 3, wn = wid & 7;     // 2(M) x 8(N), warp 64x32

    float acc[4][4][4];
    #pragma unroll
    for (int i = 0; i < 4; i++)
        #pragma unroll
        for (int j = 0; j < 4; j++)
            #pragma unroll
            for (int t = 0; t < 4; t++) acc[i][j][t] = 0.f;

    const int iters = Kc >> 5;

    auto fillA = [&](int stage, int kit) {
        const int k0 = kbase + (kit << 5);
        const uint32_t abase = sb + stage * STAGE_B;
        #pragma unroll
        for (int i = 0; i < 2; i++) {
            int idx = tid + i * 512;
            int r = idx >> 3, c = idx & 7;
            uint32_t dst = abase + r * 128 + ((c ^ (r & 7)) << 4);
            const __nv_bfloat16* src = (c < 4)
                ? Ah + (size_t)arow[i] * K + k0 + c * 8
                : Al + (size_t)arow[i] * K + k0 + (c - 4) * 8;
            cp_async16(dst, src, 16);
        }
        CP_COMMIT();
    };

    auto ldgB = [&](float4* breg, int kit) {
        const int k0 = kbase + (kit << 5);
        #pragma unroll
        for (int i = 0; i < 2; i++) {
            int idx = tid + i * 512;
            int r = idx >> 2, c2 = idx & 3;
            int rg = n0 + r;
            int rc = rg < N ? rg : (N - 1);
            const float* Bp; int rr;
            if (MODE == 1)          { Bp = (rc & 1) ? b1p : b0p; rr = rc >> 1; }
            else if (rc < rPB)      { Bp = b0p; rr = rc; }
            else if (rc < 2 * rPB)  { Bp = b1p; rr = rc - rPB; }
            else                    { Bp = b2p; rr = rc - 2 * rPB; }
            const float4* s4 = (const float4*)(Bp + (size_t)rr * K + k0 + c2 * 8);
            breg[i*2]     = s4[0];
            breg[i*2 + 1] = s4[1];
        }
    };

    auto stsB = [&](const float4* breg, int stage) {
        const uint32_t bbase = sb + stage * STAGE_B + A_BYTES;
        #pragma unroll
        for (int i = 0; i < 2; i++) {
            int idx = tid + i * 512;
            int r = idx >> 2, c2 = idx & 3;
            float4 v0 = breg[i*2], v1 = breg[i*2 + 1];
            uint32_t h0, h1, h2, h3, l0, l1, l2, l3;
            split2(v0.x, v0.y, h0, l0);
            split2(v0.z, v0.w, h1, l1);
            split2(v1.x, v1.y, h2, l2);
            split2(v1.z, v1.w, h3, l3);
            uint32_t ha = bbase + r * 128 + ((c2 ^ (r & 7)) << 4);
            uint32_t la = bbase + r * 128 + (((c2 + 4) ^ (r & 7)) << 4);
            STS128(ha, h0, h1, h2, h3);
            STS128(la, l0, l1, l2, l3);
        }
    };

    {
        float4 pb[4];
        #pragma unroll
        for (int s = 0; s < NSTG_TC - 1; s++) {
            fillA(s, s);
            ldgB(pb, s);
            stsB(pb, s);
        }
    }

    const int grp = lid >> 3;
    const int rin = lid & 7;
    float4 breg[4];

    for (int i = 0; i < iters; i++) {
        const int s = i % NSTG_TC;
        const bool pre = (i + NSTG_TC - 1 < iters);
        if (pre) ldgB(breg, i + NSTG_TC - 1);

        asm volatile("cp.async.wait_group %0;\n" :: "n"(NSTG_TC - 2));
        __syncthreads();

        if (pre) {
            fillA((i + NSTG_TC - 1) % NSTG_TC, i + NSTG_TC - 1);
            stsB(breg, (i + NSTG_TC - 1) % NSTG_TC);  // target stage's prior readers fenced by barrier
        } else {
            CP_COMMIT();
        }

        const uint32_t abase = sb + s * STAGE_B;
        const uint32_t bbase = abase + A_BYTES;

        #pragma unroll
        for (int g = 0; g < 2; g++) {
            uint32_t ah[4][4], bh[4][2];
            #pragma unroll
            for (int mt = 0; mt < 4; mt++) {
                int row = wm * 64 + mt * 16 + (grp & 1) * 8 + rin;
                int kch = 2 * g + (grp >> 1);
                uint32_t ad = abase + row * 128 + ((kch ^ (row & 7)) << 4);
                ldsm_x4(ah[mt][0], ah[mt][1], ah[mt][2], ah[mt][3], ad);
            }
            #pragma unroll
            for (int p = 0; p < 2; p++) {
                int tile = 2 * p + (grp >> 1);
                int row  = wn * 32 + tile * 8 + rin;
                int kch  = 2 * g + (grp & 1);
                uint32_t bd = bbase + row * 128 + ((kch ^ (row & 7)) << 4);
                ldsm_x4(bh[2*p][0], bh[2*p][1], bh[2*p+1][0], bh[2*p+1][1], bd);
            }
            #pragma unroll
            for (int mt = 0; mt < 4; mt++)
                #pragma unroll
                for (int nt = 0; nt < 4; nt++)
                    mma_bf16(acc[mt][nt], ah[mt], bh[nt]);
            {
                uint32_t al[4][4];
                #pragma unroll
                for (int mt = 0; mt < 4; mt++) {
                    int row = wm * 64 + mt * 16 + (grp & 1) * 8 + rin;
                    int kcl = 4 + 2 * g + (grp >> 1);
                    uint32_t adl = abase + row * 128 + ((kcl ^ (row & 7)) << 4);
                    ldsm_x4(al[mt][0], al[mt][1], al[mt][2], al[mt][3], adl);
                }
                #pragma unroll
                for (int mt = 0; mt < 4; mt++)
                    #pragma unroll
                    for (int nt = 0; nt < 4; nt++)
                        mma_bf16(acc[mt][nt], al[mt], bh[nt]);
            }
            {
                uint32_t bl[4][2];
                #pragma unroll
                for (int p = 0; p < 2; p++) {
                    int tile = 2 * p + (grp >> 1);
                    int row  = wn * 32 + tile * 8 + rin;
                    int kcl  = 4 + 2 * g + (grp & 1);
                    uint32_t bdl = bbase + row * 128 + ((kcl ^ (row & 7)) << 4);
                    ldsm_x4(bl[2*p][0], bl[2*p][1], bl[2*p+1][0], bl[2*p+1][1], bdl);
                }
                #pragma unroll
                for (int mt = 0; mt < 4; mt++)
                    #pragma unroll
                    for (int nt = 0; nt < 4; nt++)
                        mma_bf16(acc[mt][nt], ah[mt], bl[nt]);
            }
        }
    }

    #pragma unroll
    for (int mt = 0; mt < 4; mt++) {
        #pragma unroll
        for (int nt = 0; nt < 4; nt++) {
            int rbase = m0 + wm * 64 + mt * 16 + (lid >> 2);
            int col = n0 + wn * 32 + nt * 8 + (lid & 3) * 2;
            #pragma unroll
            for (int h = 0; h < 2; h++) {
                int m = rbase + h * 8;
                float v0 = acc[mt][nt][h * 2 + 0];
                float v1 = acc[mt][nt][h * 2 + 1];
                if (MODE == 1) {
                    if (m < M) {
                        int j = col >> 1;
                        float r = v0 / (1.f + expf(-v0)) * v1;
                        Hout[(size_t)e * SEQ * D_FFN + (size_t)m * D_FFN + j] = r;
                    }
                } else {
                    size_t idx = (size_t)m * N + col;
                    if (col     < N) atomicAdd(&C[idx],     v0);
                    if (col + 1 < N) atomicAdd(&C[idx + 1], v1);
                }
            }
        }
    }
}

// ================= tf32 GEMM (head: MOE=0, moe-down: MOE=1), 512 threads =================
template<int MOE>
__global__ void __launch_bounds__(512, 1) gemm_tf32(
    const float* __restrict__ Ain, const float* __restrict__ Bin,
    float* __restrict__ C, int N, int K,
    const int* __restrict__ cntArr, const int* __restrict__ ridxAll,
    const float* __restrict__ rwtAll)
{
    const int tid = threadIdx.x;
    const int m0  = blockIdx.x * 128;
    const int n0  = blockIdx.y * 256;

    int M = SEQ;
    int e = 0, ks = 0, kbase = 0, Kc = K;
    const int* ridx = ridxAll;
    const float* rwt = rwtAll;
    const float* A = Ain;
    const float* B = Bin;
    if (MOE) {
        e  = blockIdx.z >> 2;
        ks = blockIdx.z & 3;
        M  = cntArr[e];
        if (m0 >= M) return;
        ridx = ridxAll + e * SEQ;
        rwt  = rwtAll + e * SEQ;
        A = Ain + (size_t)e * SEQ * D_FFN;
        B = Bin + (size_t)e * (size_t)D_FFN * D_MODEL;
        Kc = K >> 2;
        kbase = ks * Kc;
    }

    int arow[2];
    #pragma unroll
    for (int i = 0; i < 2; i++) {
        int r = (tid + i * 512) >> 3;
        int rg = m0 + r;
        arow[i] = (MOE && rg >= M) ? (M - 1) : rg;
    }

    extern __shared__ char smem[];
    const uint32_t sb = smem_u32(smem);
    const int wid = tid >> 5, lid = tid & 31;
    const int wm  = wid >> 3, wn = wid & 7;

    float acc[4][4][4];
    #pragma unroll
    for (int i = 0; i < 4; i++)
        #pragma unroll
        for (int j = 0; j < 4; j++)
            #pragma unroll
            for (int t = 0; t < 4; t++) acc[i][j][t] = 0.f;

    const int iters = Kc >> 5;

    auto fill = [&](int stage, int kit) {
        const int k0 = kbase + (kit << 5);
        const uint32_t abase = sb + stage * STAGE_B;
        const uint32_t bbase = abase + A_BYTES;
        #pragma unroll
        for (int i = 0; i < 2; i++) {
            int idx = tid + i * 512;
            int r = idx >> 3, c = idx & 7;
            uint32_t dst = abase + r * 128 + ((c ^ (r & 7)) << 4);
            cp_async16(dst, A + (size_t)arow[i] * K + k0 + c * 4, 16);
        }
        #pragma unroll
        for (int i = 0; i < 4; i++) {
            int idx = tid + i * 512;
            int r = idx >> 3, c = idx & 7;
            uint32_t dst = bbase + r * 128 + ((c ^ (r & 7)) << 4);
            int rg = n0 + r;
            int rc = rg < N ? rg : (N - 1);
            cp_async16(dst, B + (size_t)rc * K + k0 + c * 4, rg < N ? 16 : 0);
        }
        CP_COMMIT();
    };

    #pragma unroll
    for (int s = 0; s < NSTG_TF - 1; s++) fill(s, s);

    const int grp = lid >> 3;
    const int rin = lid & 7;

    for (int i = 0; i < iters; i++) {
        const int s = i % NSTG_TF;
        asm volatile("cp.async.wait_group %0;\n" :: "n"(NSTG_TF - 2));
        __syncthreads();

        if (i + NSTG_TF - 1 < iters) fill((i + NSTG_TF - 1) % NSTG_TF, i + NSTG_TF - 1);
        else CP_COMMIT();

        const uint32_t abase = sb + s * STAGE_B;
        const uint32_t bbase = abase + A_BYTES;

        #pragma unroll
        for (int k8 = 0; k8 < 4; k8++) {
            uint32_t a[4][4], b[4][2];
            #pragma unroll
            for (int mt = 0; mt < 4; mt++) {
                int row = wm * 64 + mt * 16 + (grp & 1) * 8 + rin;
                int kc  = k8 * 2 + (grp >> 1);
                uint32_t addr = abase + row * 128 + ((kc ^ (row & 7)) << 4);
                ldsm_x4(a[mt][0], a[mt][1], a[mt][2], a[mt][3], addr);
            }
            #pragma unroll
            for (int p = 0; p < 2; p++) {
                int tile = 2 * p + (grp >> 1);
                int row  = wn * 32 + tile * 8 + rin;
                int kc   = k8 * 2 + (grp & 1);
                uint32_t addr = bbase + row * 128 + ((kc ^ (row & 7)) << 4);
                ldsm_x4(b[2*p][0], b[2*p][1], b[2*p+1][0], b[2*p+1][1], addr);
            }
            #pragma unroll
            for (int mt = 0; mt < 4; mt++)
                #pragma unroll
                for (int nt = 0; nt < 4; nt++)
                    mma_tf32(acc[mt][nt], a[mt], b[nt]);
        }
    }

    #pragma unroll
    for (int mt = 0; mt < 4; mt++) {
        #pragma unroll
        for (int nt = 0; nt < 4; nt++) {
            int rbase = m0 + wm * 64 + mt * 16 + (lid >> 2);
            int col = n0 + wn * 32 + nt * 8 + (lid & 3) * 2;
            #pragma unroll
            for (int h = 0; h < 2; h++) {
                int m = rbase + h * 8;
                float v0 = acc[mt][nt][h * 2 + 0];
                float v1 = acc[mt][nt][h * 2 + 1];
                if (!MOE) {
                    size_t idx = (size_t)m * N + col;
                    if (col     < N) C[idx]     = v0;
                    if (col + 1 < N) C[idx + 1] = v1;
                } else if (m < M) {
                    int tok = ridx[m];
                    float w = rwt[m];
                    size_t idx = (size_t)tok * N + col;
                    atomicAdd(&C[idx],     w * v0);
                    atomicAdd(&C[idx + 1], w * v1);
                }
            }
        }
    }
}

// ---------------- embedding (+ fused split) ----------------
__global__ void embed_kernel(const int* __restrict__ tok,
                             const float* __restrict__ emb,
                             float* __restrict__ x,
                             __nv_bfloat16* __restrict__ ah,
                             __nv_bfloat16* __restrict__ al) {
    int t = blockIdx.x;
    int tk = tok[t];
    const float2* src = (const float2*)(emb + (size_t)tk * D_MODEL);
    float2* dst = (float2*)(x + (size_t)t * D_MODEL);
    uint32_t* hd = (uint32_t*)(ah + (size_t)t * D_MODEL);
    uint32_t* ld = (uint32_t*)(al + (size_t)t * D_MODEL);
    for (int p = threadIdx.x; p < D_MODEL/2; p += 256) {
        float2 v = src[p];
        dst[p] = v;
        uint32_t h, l;
        split2(v.x, v.y, h, l);
        hd[p] = h;
        ld[p] = l;
    }
}

// ---------------- RoPE ----------------
__global__ void rope_kernel(float* __restrict__ qkv) {
    int t = blockIdx.x, h = blockIdx.y, i = threadIdx.x;
    float inv = powf(10000.f, -((float)(2*i)) / 64.f);
    float ang = (float)t * inv;
    float s, c;
    sincosf(ang, &s, &c);
    size_t base = (size_t)t*QKV_STRIDE + h*HEAD_DIM + 2*i;
    float q0 = qkv[base], q1 = qkv[base+1];
    qkv[base]   = q0*c - q1*s;
    qkv[base+1] = q0*s + q1*c;
    size_t kb = base + D_MODEL;
    float k0 = qkv[kb], k1 = qkv[kb+1];
    qkv[kb]   = k0*c - k1*s;
    qkv[kb+1] = k0*s + k1*c;
}

// ---------------- blocked attention: 4x4 register tiles ----------------
#define ATTN_SMEM (4 * 64 * 68 * 4)
__global__ void __launch_bounds__(256) attn_kernel(
    const float* __restrict__ qkv,
    __nv_bfloat16* __restrict__ oh, __nv_bfloat16* __restrict__ ol)
{
    extern __shared__ float sm[];
    float* Qst = sm;
    float* Kst = Qst + 64*68;
    float* Vs  = Kst + 64*68;
    float* Pst = Vs + 64*68;
    const int ib = blockIdx.x, h = blockIdx.y;
    const int tid = threadIdx.x;
    const int qg  = tid >> 4;
    const int cg  = tid & 15;
    const int qr0 = qg * 4;
    const int c0  = cg * 4;

    for (int idx = tid; idx < 64*64; idx += 256) {
        int r = idx >> 6, c = idx & 63;
        Qst[c*68 + r] = qkv[(size_t)(ib*64+r)*QKV_STRIDE + h*HEAD_DIM + c];
    }

    float accO[4][4];
    #pragma unroll
    for (int i = 0; i < 4; i++)
        #pragma unroll
        for (int j = 0; j < 4; j++) accO[i][j] = 0.f;
    float den[4] = {0.f, 0.f, 0.f, 0.f};

    for (int jb = 0; jb <= ib; jb++) {
        __syncthreads();
        for (int idx = tid; idx < 64*64; idx += 256) {
            int r = idx >> 6, c = idx & 63;
            size_t base = (size_t)(jb*64+r)*QKV_STRIDE + h*HEAD_DIM + c;
            Kst[c*68 + r] = qkv[base + D_MODEL];
            Vs [r*68 + c] = qkv[base + 2*D_MODEL];
        }
        __syncthreads();

        float s4[4][4];
        #pragma unroll
        for (int i = 0; i < 4; i++)
            #pragma unroll
            for (int j = 0; j < 4; j++) s4[i][j] = 0.f;

        #pragma unroll 4
        for (int d = 0; d < 64; d++) {
            float4 qv = *(const float4*)&Qst[d*68 + qr0];
            float4 kv = *(const float4*)&Kst[d*68 + c0];
            s4[0][0] = fmaf(qv.x, kv.x, s4[0][0]); s4[0][1] = fmaf(qv.x, kv.y, s4[0][1]);
            s4[0][2] = fmaf(qv.x, kv.z, s4[0][2]); s4[0][3] = fmaf(qv.x, kv.w, s4[0][3]);
            s4[1][0] = fmaf(qv.y, kv.x, s4[1][0]); s4[1][1] = fmaf(qv.y, kv.y, s4[1][1]);
            s4[1][2] = fmaf(qv.y, kv.z, s4[1][2]); s4[1][3] = fmaf(qv.y, kv.w, s4[1][3]);
            s4[2][0] = fmaf(qv.z, kv.x, s4[2][0]); s4[2][1] = fmaf(qv.z, kv.y, s4[2][1]);
            s4[2][2] = fmaf(qv.z, kv.z, s4[2][2]); s4[2][3] = fmaf(qv.z, kv.w, s4[2][3]);
            s4[3][0] = fmaf(qv.w, kv.x, s4[3][0]); s4[3][1] = fmaf(qv.w, kv.y, s4[3][1]);
            s4[3][2] = fmaf(qv.w, kv.z, s4[3][2]); s4[3][3] = fmaf(qv.w, kv.w, s4[3][3]);
        }

        float mx[4];
        #pragma unroll
        for (int i = 0; i < 4; i++) {
            mx[i] = -1e30f;
            int q = qr0 + i;
            #pragma unroll
            for (int j = 0; j < 4; j++) {
                int c = c0 + j;
                float v = s4[i][j] * 0.125f;
                if (jb == ib && c > q) v = -1e30f;
                s4[i][j] = v;
                mx[i] = fmaxf(mx[i], v);
            }
        }
        #pragma unroll
        for (int o = 1; o < 16; o <<= 1) {
            #pragma unroll
            for (int i = 0; i < 4; i++)
                mx[i] = fmaxf(mx[i], __shfl_xor_sync(0xffffffffu, mx[i], o));
        }

        #pragma unroll
        for (int j = 0; j < 4; j++) {
            float p0 = expf(s4[0][j] - mx[0]);
            float p1 = expf(s4[1][j] - mx[1]);
            float p2 = expf(s4[2][j] - mx[2]);
            float p3 = expf(s4[3][j] - mx[3]);
            den[0] += p0; den[1] += p1; den[2] += p2; den[3] += p3;
            *(float4*)&Pst[(c0 + j)*68 + qr0] = make_float4(p0, p1, p2, p3);
        }
        __syncthreads();

        #pragma unroll 4
        for (int kk = 0; kk < 64; kk++) {
            float4 pv = *(const float4*)&Pst[kk*68 + qr0];
            float4 vv = *(const float4*)&Vs [kk*68 + c0];
            accO[0][0] = fmaf(pv.x, vv.x, accO[0][0]); accO[0][1] = fmaf(pv.x, vv.y, accO[0][1]);
            accO[0][2] = fmaf(pv.x, vv.z, accO[0][2]); accO[0][3] = fmaf(pv.x, vv.w, accO[0][3]);
            accO[1][0] = fmaf(pv.y, vv.x, accO[1][0]); accO[1][1] = fmaf(pv.y, vv.y, accO[1][1]);
            accO[1][2] = fmaf(pv.y, vv.z, accO[1][2]); accO[1][3] = fmaf(pv.y, vv.w, accO[1][3]);
            accO[2][0] = fmaf(pv.z, vv.x, accO[2][0]); accO[2][1] = fmaf(pv.z, vv.y, accO[2][1]);
            accO[2][2] = fmaf(pv.z, vv.z, accO[2][2]); accO[2][3] = fmaf(pv.z, vv.w, accO[2][3]);
            accO[3][0] = fmaf(pv.w, vv.x, accO[3][0]); accO[3][1] = fmaf(pv.w, vv.y, accO[3][1]);
            accO[3][2] = fmaf(pv.w, vv.z, accO[3][2]); accO[3][3] = fmaf(pv.w, vv.w, accO[3][3]);
        }
    }

    #pragma unroll
    for (int o = 1; o < 16; o <<= 1) {
        #pragma unroll
        for (int i = 0; i < 4; i++)
            den[i] += __shfl_xor_sync(0xffffffffu, den[i], o);
    }

    #pragma unroll
    for (int i = 0; i < 4; i++) {
        float invd = 1.f / (den[i] + 1e-6f);
        size_t obase = (size_t)(ib*64 + qr0 + i)*D_MODEL + h*HEAD_DIM + c0;
        uint32_t h0, l0, h1, l1;
        split2(accO[i][0]*invd, accO[i][1]*invd, h0, l0);
        split2(accO[i][2]*invd, accO[i][3]*invd, h1, l1);
        uint32_t* hd = (uint32_t*)(oh + obase);
        uint32_t* ld = (uint32_t*)(ol + obase);
        hd[0] = h0; hd[1] = h1;
        ld[0] = l0; ld[1] = l1;
    }
}

// ---------------- layernorm (optional residual, optional split output) ----------------
__global__ void __launch_bounds__(256) ln_kernel(
    const float* __restrict__ in, const float* __restrict__ res,
    const float* __restrict__ g, const float* __restrict__ b,
    float* __restrict__ out,
    __nv_bfloat16* __restrict__ hi, __nv_bfloat16* __restrict__ lo)
{
    __shared__ float red[256];
    int t = blockIdx.x, tid = threadIdx.x;
    float v[8];
    float sum = 0.f;
    #pragma unroll
    for (int i = 0; i < 8; i++) {
        int d = i*256 + tid;
        float x = in[(size_t)t*D_MODEL + d];
        if (res) x += res[(size_t)t*D_MODEL + d];
        v[i] = x; sum += x;
    }
    red[tid] = sum; __syncthreads();
    for (int s = 128; s > 0; s >>= 1) { if (tid < s) red[tid] += red[tid+s]; __syncthreads(); }
    float mu = red[0] / D_MODEL;
    __syncthreads();
    float sq = 0.f;
    #pragma unroll
    for (int i = 0; i < 8; i++) { float d0 = v[i] - mu; sq += d0*d0; }
    red[tid] = sq; __syncthreads();
    for (int s = 128; s > 0; s >>= 1) { if (tid < s) red[tid] += red[tid+s]; __syncthreads(); }
    float rstd = rsqrtf(red[0] / D_MODEL + 1e-5f);
    #pragma unroll
    for (int i = 0; i < 8; i++) {
        int d = i*256 + tid;
        float val = (v[i] - mu) * rstd * g[d] + b[d];
        out[(size_t)t*D_MODEL + d] = val;
        if (hi) {
            __nv_bfloat16 hv = __float2bfloat16(val);
            hi[(size_t)t*D_MODEL + d] = hv;
            lo[(size_t)t*D_MODEL + d] = __float2bfloat16(val - __bfloat162float(hv));
        }
    }
}

// ---------------- fused double layernorm ----------------
__global__ void __launch_bounds__(256) ln2_kernel(
    const float* __restrict__ in, const float* __restrict__ res,
    const float* __restrict__ g2, const float* __restrict__ b2,
    const float* __restrict__ gf, const float* __restrict__ bf,
    float* __restrict__ out)
{
    __shared__ float red[256];
    int t = blockIdx.x, tid = threadIdx.x;
    float v[8];
    float sum = 0.f;
    #pragma unroll
    for (int i = 0; i < 8; i++) {
        int d = i*256 + tid;
        float x = in[(size_t)t*D_MODEL + d] + res[(size_t)t*D_MODEL + d];
        v[i] = x; sum += x;
    }
    red[tid] = sum; __syncthreads();
    for (int s = 128; s > 0; s >>= 1) { if (tid < s) red[tid] += red[tid+s]; __syncthreads(); }
    float mu = red[0] / D_MODEL;
    __syncthreads();
    float sq = 0.f;
    #pragma unroll
    for (int i = 0; i < 8; i++) { float d0 = v[i] - mu; sq += d0*d0; }
    red[tid] = sq; __syncthreads();
    for (int s = 128; s > 0; s >>= 1) { if (tid < s) red[tid] += red[tid+s]; __syncthreads(); }
    float rstd = rsqrtf(red[0] / D_MODEL + 1e-5f);
    __syncthreads();
    float sum2 = 0.f;
    #pragma unroll
    for (int i = 0; i < 8; i++) {
        int d = i*256 + tid;
        v[i] = (v[i] - mu) * rstd * g2[d] + b2[d];
        sum2 += v[i];
    }
    red[tid] = sum2; __syncthreads();
    for (int s = 128; s > 0; s >>= 1) { if (tid < s) red[tid] += red[tid+s]; __syncthreads(); }
    float mu2 = red[0] / D_MODEL;
    __syncthreads();
    float sq2 = 0.f;
    #pragma unroll
    for (int i = 0; i < 8; i++) { float d0 = v[i] - mu2; sq2 += d0*d0; }
    red[tid] = sq2; __syncthreads();
    for (int s = 128; s > 0; s >>= 1) { if (tid < s) red[tid] += red[tid+s]; __syncthreads(); }
    float rstd2 = rsqrtf(red[0] / D_MODEL + 1e-5f);
    #pragma unroll
    for (int i = 0; i < 8; i++) {
        int d = i*256 + tid;
        out[(size_t)t*D_MODEL + d] = (v[i] - mu2) * rstd2 * gf[d] + bf[d];
    }
}

// ---------------- MoE gate ----------------
__global__ void __launch_bounds__(128) gate_kernel(
    const float* __restrict__ x, const float* __restrict__ gw,
    float* __restrict__ wts, float* __restrict__ varr)
{
    __shared__ float red[128];
    __shared__ float logit[4];
    int t = blockIdx.x, tid = threadIdx.x;
    float p[4] = {0.f, 0.f, 0.f, 0.f};
    for (int d = tid; d < D_MODEL; d += 128) {
        float xv = x[(size_t)t*D_MODEL + d];
        #pragma unroll
        for (int e = 0; e < 4; e++)
            p[e] = fmaf(xv, gw[e*D_MODEL + d], p[e]);
    }
    for (int e = 0; e < 4; e++) {
        red[tid] = p[e]; __syncthreads();
        for (int s = 64; s > 0; s >>= 1) { if (tid < s) red[tid] += red[tid+s]; __syncthreads(); }
        if (tid == 0) logit[e] = red[0];
        __syncthreads();
    }
    if (tid == 0) {
        float l[4] = {logit[0], logit[1], logit[2], logit[3]};
        float mx = fmaxf(fmaxf(l[0], l[1]), fmaxf(l[2], l[3]));
        float ex[4], ssum = 0.f;
        for (int e = 0; e < 4; e++) { ex[e] = expf(l[e] - mx); ssum += ex[e]; }
        float pr[4];
        for (int e = 0; e < 4; e++) pr[e] = ex[e] / ssum;
        int b1 = 0;
        for (int e = 1; e < 4; e++) if (pr[e] > pr[b1]) b1 = e;
        int b2 = -1;
        for (int e = 0; e < 4; e++) { if (e == b1) continue; if (b2 < 0 || pr[e] > pr[b2]) b2 = e; }
        float s2 = pr[b1] + pr[b2];
        float wv[4] = {0.f, 0.f, 0.f, 0.f};
        wv[b1] = pr[b1] / s2; wv[b2] = pr[b2] / s2;
        for (int e = 0; e < 4; e++) wts[e*SEQ + t] = wv[e];
        float mu = (l[0]+l[1]+l[2]+l[3]) * 0.25f;
        float va = ((l[0]-mu)*(l[0]-mu) + (l[1]-mu)*(l[1]-mu) +
                    (l[2]-mu)*(l[2]-mu) + (l[3]-mu)*(l[3]-mu)) / 3.f;
        varr[t] = va;
    }
}

// ---------------- routing compaction ----------------
__global__ void __launch_bounds__(1024) compact_kernel(
    const float* __restrict__ wts, int* __restrict__ cnt,
    int* __restrict__ ridx, float* __restrict__ rwt)
{
    __shared__ int sc[1024];
    int e = blockIdx.x, t = threadIdx.x;
    float w = wts[e*SEQ + t];
    int flag = (w != 0.f) ? 1 : 0;
    sc[t] = flag;
    __syncthreads();
    for (int off = 1; off < 1024; off <<= 1) {
        int v = (t >= off) ? sc[t - off] : 0;
        __syncthreads();
        sc[t] += v;
        __syncthreads();
    }
    if (flag) {
        int pos = sc[t] - 1;
        ridx[e*SEQ + pos] = t;
        rwt [e*SEQ + pos] = w;
    }
    if (t == 1023) cnt[e] = sc[1023];
}

__global__ void aux_kernel(const float* __restrict__ varr, float* __restrict__ out) {
    __shared__ float red[256];
    int tid = threadIdx.x;
    float s = 0.f;
    for (int i = tid; i < SEQ; i += 256) s += varr[i];
    red[tid] = s; __syncthreads();
    for (int st = 128; st > 0; st >>= 1) { if (tid < st) red[tid] += red[tid+st]; __syncthreads(); }
    if (tid == 0) out[0] = red[0] / (float)SEQ;
}

// ---------------- driver ----------------
extern "C" void kernel_launch(void* const* d_in, const int* in_sizes, int n_in,
                              void* d_out, int out_size) {
    const int*   tokens = (const int*)  d_in[0];
    const float* emb    = (const float*)d_in[1];
    const float* wq     = (const float*)d_in[2];
    const float* wk     = (const float*)d_in[3];
    const float* wv     = (const float*)d_in[4];
    const float* wo     = (const float*)d_in[5];
    const float* ln1g   = (const float*)d_in[6];
    const float* ln1b   = (const float*)d_in[7];
    const float* gatew  = (const float*)d_in[8];
    const float* w1     = (const float*)d_in[9];
    const float* w2     = (const float*)d_in[10];
    const float* w3     = (const float*)d_in[11];
    const float* ln2g   = (const float*)d_in[12];
    const float* ln2b   = (const float*)d_in[13];
    const float* fing   = (const float*)d_in[14];
    const float* finb   = (const float*)d_in[15];
    const float* headw  = (const float*)d_in[16];
    float* out = (float*)d_out;

    float *x, *qkv, *y, *moe, *wts, *varr, *rwt, *hbuf;
    int *cnt, *ridx;
    __nv_bfloat16 *ah, *al;
    cudaGetSymbolAddress((void**)&x,    g_x);
    cudaGetSymbolAddress((void**)&qkv,  g_qkv);
    cudaGetSymbolAddress((void**)&y,    g_y);
    cudaGetSymbolAddress((void**)&moe,  g_moe);
    cudaGetSymbolAddress((void**)&wts,  g_wts);
    cudaGetSymbolAddress((void**)&varr, g_var);
    cudaGetSymbolAddress((void**)&hbuf, g_h);
    cudaGetSymbolAddress((void**)&cnt,  g_cnt);
    cudaGetSymbolAddress((void**)&ridx, g_ridx);
    cudaGetSymbolAddress((void**)&rwt,  g_rwt);
    cudaGetSymbolAddress((void**)&ah,   g_ah);
    cudaGetSymbolAddress((void**)&al,   g_al);

    cudaFuncSetAttribute(attn_kernel, cudaFuncAttributeMaxDynamicSharedMemorySize, ATTN_SMEM);
    cudaFuncSetAttribute(gemm_tc<1>, cudaFuncAttributeMaxDynamicSharedMemorySize, GEMM_SMEM_TC);
    cudaFuncSetAttribute(gemm_tc<3>, cudaFuncAttributeMaxDynamicSharedMemorySize, GEMM_SMEM_TC);
    cudaFuncSetAttribute(gemm_tf32<0>, cudaFuncAttributeMaxDynamicSharedMemorySize, GEMM_SMEM_TF);
    cudaFuncSetAttribute(gemm_tf32<1>, cudaFuncAttributeMaxDynamicSharedMemorySize, GEMM_SMEM_TF);

    // 1) embed (+ fused split)
    embed_kernel<<<SEQ, 256>>>(tokens, emb, x, ah, al);

    // 2) fused QKV, split-K2 atomic
    cudaMemsetAsync(qkv, 0, sizeof(float)*SEQ*3*D_MODEL);
    dim3 gQKV(SEQ/128, 3*D_MODEL/256, 2);
    gemm_tc<3><<<gQKV, 512, GEMM_SMEM_TC>>>(ah, al, wq, wk, wv, D_MODEL,
                                            qkv, 3*D_MODEL, D_MODEL,
                                            nullptr, nullptr, 0, nullptr);

    // 3) RoPE + attention
    rope_kernel<<<dim3(SEQ, N_HEADS), 32>>>(qkv);
    attn_kernel<<<dim3(NB, N_HEADS), 256, ATTN_SMEM>>>(qkv, ah, al);

    // 4) output proj, split-K4 atomic -> y
    cudaMemsetAsync(y, 0, sizeof(float)*SEQ*D_MODEL);
    dim3 gA(SEQ/128, D_MODEL/256, 4);
    gemm_tc<3><<<gA, 512, GEMM_SMEM_TC>>>(ah, al, wo, wo, wo, D_MODEL,
                                          y, D_MODEL, D_MODEL,
                                          nullptr, nullptr, 0, nullptr);

    // 5) LN1(y + x) -> x (+ split)
    ln_kernel<<<SEQ, 256>>>(y, x, ln1g, ln1b, x, ah, al);

    // 6) gate + routing
    gate_kernel<<<SEQ, 128>>>(x, gatew, wts, varr);
    compact_kernel<<<NEXP, 1024>>>(wts, cnt, ridx, rwt);

    // 7) MoE
    cudaMemsetAsync(moe, 0, sizeof(float)*SEQ*D_MODEL);
    const long long FD = (long long)D_FFN * D_MODEL;
    dim3 gUp(SEQ/128, 2*D_FFN/256, NEXP);
    gemm_tc<1><<<gUp, 512, GEMM_SMEM_TC>>>(ah, al, w1, w3, nullptr, 0,
                                           nullptr, 2*D_FFN, D_MODEL,
                                           cnt, ridx, FD, hbuf);
    dim3 gDn(SEQ/128, D_MODEL/256, NEXP*4);
    gemm_tf32<1><<<gDn, 512, GEMM_SMEM_TF>>>(hbuf, w2, moe, D_MODEL, D_FFN,
                                             cnt, ridx, rwt);

    // 8) fused LN2 + final LN
    ln2_kernel<<<SEQ, 256>>>(moe, x, ln2g, ln2b, fing, finb, y);

    // 9) head
    dim3 gH(SEQ/128, (VOCAB + 255)/256);
    gemm_tf32<0><<<gH, 512, GEMM_SMEM_TF>>>(y, headw, out, VOCAB, D_MODEL,
                                            nullptr, nullptr, nullptr);

    // 10) aux
    long long nlog = (long long)SEQ * VOCAB;
    if ((long long)out_size > nlog)
        aux_kernel<<<1, 256>>>(varr, out + nlog);
}